// round 2
// baseline (speedup 1.0000x reference)
#include <cuda_runtime.h>

typedef unsigned long long ull;

static constexpr int T  = 256;
static constexpr int F  = 16;
static constexpr int U1 = 24;
static constexpr int U2 = 48;
#define LN_EPS 1e-3f

// ---------------- packed f32x2 helpers ----------------
__device__ __forceinline__ ull pk2(float lo, float hi) {
    ull r; asm("mov.b64 %0, {%1, %2};" : "=l"(r) : "f"(lo), "f"(hi)); return r;
}
__device__ __forceinline__ ull dup2(float v) { return pk2(v, v); }
__device__ __forceinline__ float2 un2(ull p) {
    float2 r; asm("mov.b64 {%0, %1}, %2;" : "=f"(r.x), "=f"(r.y) : "l"(p)); return r;
}
__device__ __forceinline__ ull ffma2(ull a, ull b, ull c) {
    ull d; asm("fma.rn.f32x2 %0, %1, %2, %3;" : "=l"(d) : "l"(a), "l"(b), "l"(c)); return d;
}
__device__ __forceinline__ ull fadd2(ull a, ull b) {
    ull d; asm("add.rn.f32x2 %0, %1, %2;" : "=l"(d) : "l"(a), "l"(b)); return d;
}
__device__ __forceinline__ ull fmul2(ull a, ull b) {
    ull d; asm("mul.rn.f32x2 %0, %1, %2;" : "=l"(d) : "l"(a), "l"(b)); return d;
}

// branch-free accurate tanh: 1 - 2/(1+e^{2x});  e->inf => 1, e->0 => -1. ~5 instrs.
__device__ __forceinline__ float tanh_f(float x) {
    float e = __expf(2.0f * x);
    return 1.0f - __fdividef(2.0f, 1.0f + e);
}

// ---------------- constant-bank weights ----------------
// All matrices pre-packed as f32x2 unit-pairs, per-warp-slice major, LN1 folded into W2.
struct __align__(16) CW {
    ull W1 [4][16][4];   // warp w, k, pair j (j<3 used): units 6w+2j, 6w+2j+1
    ull Wr1[4][24][4];
    ull W2 [4][24][6];   // g1-folded; units 12w+2j
    ull Wr2[4][48][6];
    ull B1 [4][4];       // b1 pairs per warp slice
    ull Br1[4][4];
    ull Br2[4][6];
    ull B2f[4][6];       // b2 + be1@W2
    ull C  [4][6];       // column sums of folded W2
    ull G2 [24];         // epilogue pairs over 48 units
    ull Be2[24];
    ull Wo [24];
    float bout;
    float pad[3];
};
__constant__ CW cw;
__device__ CW d_stage;

// ---------------- prep kernel: fold + pack into staging ----------------
__global__ void prep_kernel(const float* __restrict__ W1,  const float* __restrict__ b1,
                            const float* __restrict__ Wr1, const float* __restrict__ br1,
                            const float* __restrict__ g1,  const float* __restrict__ be1,
                            const float* __restrict__ W2,  const float* __restrict__ b2,
                            const float* __restrict__ Wr2, const float* __restrict__ br2,
                            const float* __restrict__ g2,  const float* __restrict__ be2,
                            const float* __restrict__ Wout, const float* __restrict__ bout)
{
    const int tid = threadIdx.x;  // 256 threads

    // W1 [16][24] -> W1[w][k][j]
    for (int idx = tid; idx < 4 * 16 * 4; idx += 256) {
        int w = idx >> 6, k = (idx >> 2) & 15, j = idx & 3;
        float lo = 0.f, hi = 0.f;
        if (j < 3) { int u = 6 * w + 2 * j; lo = W1[k * U1 + u]; hi = W1[k * U1 + u + 1]; }
        d_stage.W1[w][k][j] = ((ull)__float_as_uint(hi) << 32) | __float_as_uint(lo);
    }
    // Wr1 [24][24]
    for (int idx = tid; idx < 4 * 24 * 4; idx += 256) {
        int w = idx / 96, k = (idx / 4) % 24, j = idx & 3;
        float lo = 0.f, hi = 0.f;
        if (j < 3) { int u = 6 * w + 2 * j; lo = Wr1[k * U1 + u]; hi = Wr1[k * U1 + u + 1]; }
        d_stage.Wr1[w][k][j] = ((ull)__float_as_uint(hi) << 32) | __float_as_uint(lo);
    }
    // W2 [24][48] folded by g1
    for (int idx = tid; idx < 4 * 24 * 6; idx += 256) {
        int w = idx / 144, k = (idx / 6) % 24, j = idx % 6;
        int u = 12 * w + 2 * j;
        float lo = g1[k] * W2[k * U2 + u];
        float hi = g1[k] * W2[k * U2 + u + 1];
        d_stage.W2[w][k][j] = ((ull)__float_as_uint(hi) << 32) | __float_as_uint(lo);
    }
    // Wr2 [48][48]
    for (int idx = tid; idx < 4 * 48 * 6; idx += 256) {
        int w = idx / 288, k = (idx / 6) % 48, j = idx % 6;
        int u = 12 * w + 2 * j;
        d_stage.Wr2[w][k][j] = ((ull)__float_as_uint(Wr2[k * U2 + u + 1]) << 32)
                             | __float_as_uint(Wr2[k * U2 + u]);
    }
    // biases / fold constants
    for (int idx = tid; idx < 4 * 4; idx += 256) {
        int w = idx >> 2, j = idx & 3;
        float l1 = 0.f, h1 = 0.f, l2 = 0.f, h2 = 0.f;
        if (j < 3) { int u = 6 * w + 2 * j;
            l1 = b1[u]; h1 = b1[u + 1]; l2 = br1[u]; h2 = br1[u + 1]; }
        d_stage.B1[w][j]  = ((ull)__float_as_uint(h1) << 32) | __float_as_uint(l1);
        d_stage.Br1[w][j] = ((ull)__float_as_uint(h2) << 32) | __float_as_uint(l2);
    }
    for (int idx = tid; idx < 4 * 6; idx += 256) {
        int w = idx / 6, j = idx % 6;
        int u = 12 * w + 2 * j;
        // b2f[u] = b2[u] + sum_k be1[k]*W2[k][u];  C[u] = sum_k g1[k]*W2[k][u]
        float bfl = b2[u], bfh = b2[u + 1], cl = 0.f, ch = 0.f;
        for (int k = 0; k < U1; ++k) {
            bfl += be1[k] * W2[k * U2 + u];
            bfh += be1[k] * W2[k * U2 + u + 1];
            cl  += g1[k] * W2[k * U2 + u];
            ch  += g1[k] * W2[k * U2 + u + 1];
        }
        d_stage.Br2[w][j] = ((ull)__float_as_uint(br2[u + 1]) << 32) | __float_as_uint(br2[u]);
        d_stage.B2f[w][j] = ((ull)__float_as_uint(bfh) << 32) | __float_as_uint(bfl);
        d_stage.C[w][j]   = ((ull)__float_as_uint(ch) << 32) | __float_as_uint(cl);
    }
    for (int idx = tid; idx < 24; idx += 256) {
        int u = 2 * idx;
        d_stage.G2[idx]  = ((ull)__float_as_uint(g2[u + 1]) << 32) | __float_as_uint(g2[u]);
        d_stage.Be2[idx] = ((ull)__float_as_uint(be2[u + 1]) << 32) | __float_as_uint(be2[u]);
        d_stage.Wo[idx]  = ((ull)__float_as_uint(Wout[u + 1]) << 32) | __float_as_uint(Wout[u]);
    }
    if (tid == 0) d_stage.bout = bout[0];
}

// ---------------- main scan kernel ----------------
// CTA: 128 threads = 4 warps x 32 lanes. lane = batch row, warp = unit slice.
__global__ __launch_bounds__(128, 2)
void rnn_main(const float* __restrict__ seq, float* __restrict__ out)
{
    __shared__ ull sx[12][32];   // x pairs       [pair][row]
    __shared__ ull sn[12][32];   // ns1 pairs
    __shared__ ull sy[24][32];   // y pairs / final ns2 pairs

    const int w = threadIdx.x >> 5;       // warp id: owns u1 pairs 3w..3w+2, u2 pairs 6w..6w+5
    const int r = threadIdx.x & 31;       // lane = row within CTA
    const int row = blockIdx.x * 32 + r;

    const float4* sp = reinterpret_cast<const float4*>(seq + (size_t)row * (T * F));
    float4 c0 = sp[0], c1 = sp[1], c2 = sp[2], c3 = sp[3];

    ull s1[3] = {0ull, 0ull, 0ull};
    ull s2[6] = {0ull, 0ull, 0ull, 0ull, 0ull, 0ull};

    for (int t = 0; t < T; ++t) {
        const int tn = (t < T - 1) ? (t + 1) : t;
        float4 n0 = sp[tn * 4 + 0], n1_ = sp[tn * 4 + 1];
        float4 n2_ = sp[tn * 4 + 2], n3 = sp[tn * 4 + 3];

        const float in[16] = {c0.x, c0.y, c0.z, c0.w, c1.x, c1.y, c1.z, c1.w,
                              c2.x, c2.y, c2.z, c2.w, c3.x, c3.y, c3.z, c3.w};

        // ---- Phase A: x = in@W1 + b1 + s1  (this warp's 3 unit-pairs) ----
        ull a0 = fadd2(s1[0], cw.B1[w][0]);
        ull a1 = fadd2(s1[1], cw.B1[w][1]);
        ull a2 = fadd2(s1[2], cw.B1[w][2]);
        #pragma unroll
        for (int k = 0; k < F; ++k) {
            ull ik = dup2(in[k]);
            a0 = ffma2(ik, cw.W1[w][k][0], a0);
            a1 = ffma2(ik, cw.W1[w][k][1], a1);
            a2 = ffma2(ik, cw.W1[w][k][2], a2);
        }
        sx[3 * w + 0][r] = a0; sx[3 * w + 1][r] = a1; sx[3 * w + 2][r] = a2;
        __syncthreads();

        // ---- Phase B: ns1 = tanh(x@Wr1 + br1) ----
        ull b0 = cw.Br1[w][0], b1a = cw.Br1[w][1], b2a = cw.Br1[w][2];
        #pragma unroll
        for (int p = 0; p < 12; ++p) {
            float2 u = un2(sx[p][r]);
            ull k0 = dup2(u.x), k1 = dup2(u.y);
            b0  = ffma2(k0, cw.Wr1[w][2 * p][0], b0);
            b1a = ffma2(k0, cw.Wr1[w][2 * p][1], b1a);
            b2a = ffma2(k0, cw.Wr1[w][2 * p][2], b2a);
            b0  = ffma2(k1, cw.Wr1[w][2 * p + 1][0], b0);
            b1a = ffma2(k1, cw.Wr1[w][2 * p + 1][1], b1a);
            b2a = ffma2(k1, cw.Wr1[w][2 * p + 1][2], b2a);
        }
        {
            float2 u0 = un2(b0), u1 = un2(b1a), u2 = un2(b2a);
            s1[0] = pk2(tanh_f(u0.x), tanh_f(u0.y));
            s1[1] = pk2(tanh_f(u1.x), tanh_f(u1.y));
            s1[2] = pk2(tanh_f(u2.x), tanh_f(u2.y));
        }
        sn[3 * w + 0][r] = s1[0]; sn[3 * w + 1][r] = s1[1]; sn[3 * w + 2][r] = s1[2];
        __syncthreads();

        // ---- Phase C: y = LN1-folded(ns1)@W2 + b2f + s2 ----
        ull np[12];
        #pragma unroll
        for (int p = 0; p < 12; ++p) np[p] = sn[p][r];
        // packed LN stats over 24 values
        ull sm2 = np[0], sq2 = fmul2(np[0], np[0]);
        #pragma unroll
        for (int p = 1; p < 12; ++p) { sm2 = fadd2(sm2, np[p]); sq2 = ffma2(np[p], np[p], sq2); }
        float2 us = un2(sm2), uq = un2(sq2);
        float mu   = (us.x + us.y) * (1.0f / 24.0f);
        float var  = fmaf(-mu, mu, (uq.x + uq.y) * (1.0f / 24.0f));
        float rstd = rsqrtf(var + LN_EPS);

        ull c0a = 0, c1a = 0, c2a = 0, c3a = 0, c4a = 0, c5a = 0;
        #pragma unroll
        for (int p = 0; p < 12; ++p) {
            float2 u = un2(np[p]);
            ull k0 = dup2(u.x), k1 = dup2(u.y);
            c0a = ffma2(k0, cw.W2[w][2 * p][0], c0a);
            c1a = ffma2(k0, cw.W2[w][2 * p][1], c1a);
            c2a = ffma2(k0, cw.W2[w][2 * p][2], c2a);
            c3a = ffma2(k0, cw.W2[w][2 * p][3], c3a);
            c4a = ffma2(k0, cw.W2[w][2 * p][4], c4a);
            c5a = ffma2(k0, cw.W2[w][2 * p][5], c5a);
            c0a = ffma2(k1, cw.W2[w][2 * p + 1][0], c0a);
            c1a = ffma2(k1, cw.W2[w][2 * p + 1][1], c1a);
            c2a = ffma2(k1, cw.W2[w][2 * p + 1][2], c2a);
            c3a = ffma2(k1, cw.W2[w][2 * p + 1][3], c3a);
            c4a = ffma2(k1, cw.W2[w][2 * p + 1][4], c4a);
            c5a = ffma2(k1, cw.W2[w][2 * p + 1][5], c5a);
        }
        {
            ull mun = dup2(-mu), rsd = dup2(rstd);
            ull yv;
            yv = ffma2(rsd, ffma2(mun, cw.C[w][0], c0a), fadd2(cw.B2f[w][0], s2[0])); sy[6 * w + 0][r] = yv;
            yv = ffma2(rsd, ffma2(mun, cw.C[w][1], c1a), fadd2(cw.B2f[w][1], s2[1])); sy[6 * w + 1][r] = yv;
            yv = ffma2(rsd, ffma2(mun, cw.C[w][2], c2a), fadd2(cw.B2f[w][2], s2[2])); sy[6 * w + 2][r] = yv;
            yv = ffma2(rsd, ffma2(mun, cw.C[w][3], c3a), fadd2(cw.B2f[w][3], s2[3])); sy[6 * w + 3][r] = yv;
            yv = ffma2(rsd, ffma2(mun, cw.C[w][4], c4a), fadd2(cw.B2f[w][4], s2[4])); sy[6 * w + 4][r] = yv;
            yv = ffma2(rsd, ffma2(mun, cw.C[w][5], c5a), fadd2(cw.B2f[w][5], s2[5])); sy[6 * w + 5][r] = yv;
        }
        __syncthreads();

        // ---- Phase D: ns2 = tanh(y@Wr2 + br2) ----
        ull d0 = cw.Br2[w][0], d1 = cw.Br2[w][1], d2 = cw.Br2[w][2];
        ull d3 = cw.Br2[w][3], d4 = cw.Br2[w][4], d5 = cw.Br2[w][5];
        #pragma unroll
        for (int p = 0; p < 24; ++p) {
            float2 u = un2(sy[p][r]);
            ull k0 = dup2(u.x), k1 = dup2(u.y);
            d0 = ffma2(k0, cw.Wr2[w][2 * p][0], d0);
            d1 = ffma2(k0, cw.Wr2[w][2 * p][1], d1);
            d2 = ffma2(k0, cw.Wr2[w][2 * p][2], d2);
            d3 = ffma2(k0, cw.Wr2[w][2 * p][3], d3);
            d4 = ffma2(k0, cw.Wr2[w][2 * p][4], d4);
            d5 = ffma2(k0, cw.Wr2[w][2 * p][5], d5);
            d0 = ffma2(k1, cw.Wr2[w][2 * p + 1][0], d0);
            d1 = ffma2(k1, cw.Wr2[w][2 * p + 1][1], d1);
            d2 = ffma2(k1, cw.Wr2[w][2 * p + 1][2], d2);
            d3 = ffma2(k1, cw.Wr2[w][2 * p + 1][3], d3);
            d4 = ffma2(k1, cw.Wr2[w][2 * p + 1][4], d4);
            d5 = ffma2(k1, cw.Wr2[w][2 * p + 1][5], d5);
        }
        {
            float2 u;
            u = un2(d0); s2[0] = pk2(tanh_f(u.x), tanh_f(u.y));
            u = un2(d1); s2[1] = pk2(tanh_f(u.x), tanh_f(u.y));
            u = un2(d2); s2[2] = pk2(tanh_f(u.x), tanh_f(u.y));
            u = un2(d3); s2[3] = pk2(tanh_f(u.x), tanh_f(u.y));
            u = un2(d4); s2[4] = pk2(tanh_f(u.x), tanh_f(u.y));
            u = un2(d5); s2[5] = pk2(tanh_f(u.x), tanh_f(u.y));
        }

        c0 = n0; c1 = n1_; c2 = n2_; c3 = n3;
        // no barrier needed here: next Phase-A writes sx (not read in D),
        // and bar after A protects B's reads; sy rewrite is gated by bar after B.
        __syncthreads();  // keep one barrier so next-iteration sy writes can't pass D's reads
    }

    // ---- epilogue: sigmoid(LN(s2; g2,be2) @ Wout + bout) ----
    #pragma unroll
    for (int j = 0; j < 6; ++j) sy[6 * w + j][r] = s2[j];
    __syncthreads();

    if (w == 0) {
        ull zp[24];
        #pragma unroll
        for (int p = 0; p < 24; ++p) zp[p] = sy[p][r];
        ull sm2 = zp[0], sq2 = fmul2(zp[0], zp[0]);
        #pragma unroll
        for (int p = 1; p < 24; ++p) { sm2 = fadd2(sm2, zp[p]); sq2 = ffma2(zp[p], zp[p], sq2); }
        float2 us = un2(sm2), uq = un2(sq2);
        float mu   = (us.x + us.y) * (1.0f / 48.0f);
        float var  = fmaf(-mu, mu, (uq.x + uq.y) * (1.0f / 48.0f));
        float rstd = rsqrtf(var + LN_EPS);
        ull mun = dup2(-mu), rsd = dup2(rstd);
        ull acc = 0;
        #pragma unroll
        for (int p = 0; p < 24; ++p) {
            ull h = fmul2(fadd2(zp[p], mun), rsd);          // (z - mu) * rstd
            h = ffma2(h, cw.G2[p], cw.Be2[p]);              // * g2 + be2
            acc = ffma2(h, cw.Wo[p], acc);                  // dot with Wout
        }
        float2 ua = un2(acc);
        float z = ua.x + ua.y + cw.bout;
        out[row] = __fdividef(1.0f, 1.0f + __expf(-z));
    }
}

extern "C" void kernel_launch(void* const* d_in, const int* in_sizes, int n_in,
                              void* d_out, int out_size)
{
    const float* seq  = (const float*)d_in[0];
    const float* W1   = (const float*)d_in[1];
    const float* b1   = (const float*)d_in[2];
    const float* Wr1  = (const float*)d_in[3];
    const float* br1  = (const float*)d_in[4];
    const float* g1   = (const float*)d_in[5];
    const float* be1  = (const float*)d_in[6];
    const float* W2   = (const float*)d_in[7];
    const float* b2   = (const float*)d_in[8];
    const float* Wr2  = (const float*)d_in[9];
    const float* br2  = (const float*)d_in[10];
    const float* g2   = (const float*)d_in[11];
    const float* be2  = (const float*)d_in[12];
    const float* Wout = (const float*)d_in[13];
    const float* bout = (const float*)d_in[14];

    prep_kernel<<<1, 256>>>(W1, b1, Wr1, br1, g1, be1,
                            W2, b2, Wr2, br2, g2, be2, Wout, bout);

    void* stage_ptr = nullptr;
    cudaGetSymbolAddress(&stage_ptr, d_stage);
    cudaMemcpyToSymbolAsync(cw, stage_ptr, sizeof(CW), 0,
                            cudaMemcpyDeviceToDevice, 0);

    const int B = in_sizes[0] / (T * F);     // 8192
    rnn_main<<<B / 32, 128>>>(seq, (float*)d_out);
}

// round 3
// speedup vs baseline: 3.4295x; 3.4295x over previous
#include <cuda_runtime.h>

typedef unsigned long long ull;

static constexpr int T  = 256;
static constexpr int F  = 16;
static constexpr int U1 = 24;
static constexpr int U2 = 48;
#define LN_EPS 1e-3f

// ---------------- packed f32x2 helpers ----------------
__device__ __forceinline__ ull pk2(float lo, float hi) {
    ull r; asm("mov.b64 %0, {%1, %2};" : "=l"(r) : "f"(lo), "f"(hi)); return r;
}
__device__ __forceinline__ ull dup2(float v) { return pk2(v, v); }
__device__ __forceinline__ float2 un2(ull p) {
    float2 r; asm("mov.b64 {%0, %1}, %2;" : "=f"(r.x), "=f"(r.y) : "l"(p)); return r;
}
__device__ __forceinline__ ull ffma2(ull a, ull b, ull c) {
    ull d; asm("fma.rn.f32x2 %0, %1, %2, %3;" : "=l"(d) : "l"(a), "l"(b), "l"(c)); return d;
}
__device__ __forceinline__ ull fadd2(ull a, ull b) {
    ull d; asm("add.rn.f32x2 %0, %1, %2;" : "=l"(d) : "l"(a), "l"(b)); return d;
}
__device__ __forceinline__ ull fmul2(ull a, ull b) {
    ull d; asm("mul.rn.f32x2 %0, %1, %2;" : "=l"(d) : "l"(a), "l"(b)); return d;
}

// branch-free accurate tanh: 1 - 2/(1+e^{2x})
__device__ __forceinline__ float tanh_f(float x) {
    float e = __expf(2.0f * x);
    return 1.0f - __fdividef(2.0f, 1.0f + e);
}

// ---------------- packed weight bundle (global staging -> smem) ----------------
// Pair-merged rows: adjacent k-rows fused so every weight load is a 16B LDS.128.
struct __align__(16) CW {
    ull W1m [4][8][6];    // [w][kp][j]: j0..2 = k=2kp pairs, j3..5 = k=2kp+1 pairs
    ull Wr1m[4][12][6];   // [w][p][j]:  k-rows 2p, 2p+1 (3 pairs each)
    ull W2m [4][12][12];  // [w][p][j]:  j0..5 row 2p, j6..11 row 2p+1 (g1-folded)
    ull Wr2m[4][24][12];  // [w][p][j]:  rows 2p, 2p+1 (6 pairs each)
    ull B1 [4][3];        // b1 pairs per warp slice
    ull Br1[4][3];
    ull Br2[4][6];
    ull B2f[4][6];        // b2 + be1 @ W2
    ull Cc [4][6];        // column sums of folded W2
    ull G2 [24];          // epilogue pairs over 48 units
    ull Be2[24];
    ull Wo [24];
    float bout;
    float pad3[3];
};
__device__ CW d_stage;

__device__ __forceinline__ ull mkp(float lo, float hi) {
    return ((ull)__float_as_uint(hi) << 32) | __float_as_uint(lo);
}

// ---------------- prep kernel: fold LN1 into W2, pack pair-merged ----------------
__global__ void prep_kernel(const float* __restrict__ W1,  const float* __restrict__ b1,
                            const float* __restrict__ Wr1, const float* __restrict__ br1,
                            const float* __restrict__ g1,  const float* __restrict__ be1,
                            const float* __restrict__ W2,  const float* __restrict__ b2,
                            const float* __restrict__ Wr2, const float* __restrict__ br2,
                            const float* __restrict__ g2,  const float* __restrict__ be2,
                            const float* __restrict__ Wout, const float* __restrict__ bout)
{
    const int tid = threadIdx.x;  // 256 threads

    // W1m [4][8][6]
    for (int idx = tid; idx < 4 * 8 * 6; idx += 256) {
        int w = idx / 48, kp = (idx / 6) % 8, j = idx % 6;
        int k = 2 * kp + (j >= 3), u = 6 * w + 2 * (j % 3);
        d_stage.W1m[w][kp][j] = mkp(W1[k * U1 + u], W1[k * U1 + u + 1]);
    }
    // Wr1m [4][12][6]
    for (int idx = tid; idx < 4 * 12 * 6; idx += 256) {
        int w = idx / 72, p = (idx / 6) % 12, j = idx % 6;
        int k = 2 * p + (j >= 3), u = 6 * w + 2 * (j % 3);
        d_stage.Wr1m[w][p][j] = mkp(Wr1[k * U1 + u], Wr1[k * U1 + u + 1]);
    }
    // W2m [4][12][12]  (g1-folded)
    for (int idx = tid; idx < 4 * 12 * 12; idx += 256) {
        int w = idx / 144, p = (idx / 12) % 12, j = idx % 12;
        int k = 2 * p + (j >= 6), u = 12 * w + 2 * (j % 6);
        d_stage.W2m[w][p][j] = mkp(g1[k] * W2[k * U2 + u], g1[k] * W2[k * U2 + u + 1]);
    }
    // Wr2m [4][24][12]
    for (int idx = tid; idx < 4 * 24 * 12; idx += 256) {
        int w = idx / 288, p = (idx % 288) / 12, j = idx % 12;
        int k = 2 * p + (j >= 6), u = 12 * w + 2 * (j % 6);
        d_stage.Wr2m[w][p][j] = mkp(Wr2[k * U2 + u], Wr2[k * U2 + u + 1]);
    }
    // B1 / Br1 [4][3]
    for (int idx = tid; idx < 12; idx += 256) {
        int w = idx / 3, j = idx % 3, u = 6 * w + 2 * j;
        d_stage.B1[w][j]  = mkp(b1[u],  b1[u + 1]);
        d_stage.Br1[w][j] = mkp(br1[u], br1[u + 1]);
    }
    // Br2 / B2f / Cc [4][6]
    for (int idx = tid; idx < 24; idx += 256) {
        int w = idx / 6, j = idx % 6, u = 12 * w + 2 * j;
        float bfl = b2[u], bfh = b2[u + 1], cl = 0.f, ch = 0.f;
        for (int k = 0; k < U1; ++k) {
            bfl += be1[k] * W2[k * U2 + u];
            bfh += be1[k] * W2[k * U2 + u + 1];
            cl  += g1[k] * W2[k * U2 + u];
            ch  += g1[k] * W2[k * U2 + u + 1];
        }
        d_stage.Br2[w][j] = mkp(br2[u], br2[u + 1]);
        d_stage.B2f[w][j] = mkp(bfl, bfh);
        d_stage.Cc[w][j]  = mkp(cl, ch);
    }
    for (int idx = tid; idx < 24; idx += 256) {
        int u = 2 * idx;
        d_stage.G2[idx]  = mkp(g2[u],   g2[u + 1]);
        d_stage.Be2[idx] = mkp(be2[u],  be2[u + 1]);
        d_stage.Wo[idx]  = mkp(Wout[u], Wout[u + 1]);
    }
    if (tid == 0) { d_stage.bout = bout[0]; }
}

// ---------------- main scan kernel ----------------
// CTA: 128 threads = 4 warps x 32 lanes. lane = batch row, warp = unit slice.
// All weight LDS are warp-uniform => smem broadcast (1 wavefront per load).
__global__ __launch_bounds__(128, 2)
void rnn_main(const float* __restrict__ seq, float* __restrict__ out)
{
    __shared__ CW scw;
    __shared__ ull sx[12][32];            // x pairs       [pair][row]
    __shared__ ull sn[12][32];            // ns1 pairs
    __shared__ ull sy[24][32];            // y pairs / final ns2 pairs
    __shared__ float sinb[2][16][32];     // staged input  [buf][feat][row]

    const int tid = threadIdx.x;
    const int w = tid >> 5;               // warp id: u1 pairs 3w..3w+2, u2 pairs 6w..6w+5
    const int r = tid & 31;               // lane = row within CTA
    const int row = blockIdx.x * 32 + r;

    // cooperative copy of packed weights into smem
    {
        const ull* gsrc = reinterpret_cast<const ull*>(&d_stage);
        ull* sdst = reinterpret_cast<ull*>(&scw);
        const int N = (int)(sizeof(CW) / 8);
        for (int i = tid; i < N; i += 128) sdst[i] = gsrc[i];
    }

    const float4* sp4 = reinterpret_cast<const float4*>(seq + (size_t)row * (T * F));

    // stage t=0 input: warp w supplies feature chunk 4w..4w+3 for all rows
    {
        float4 f0 = sp4[w];
        sinb[0][4 * w + 0][r] = f0.x;
        sinb[0][4 * w + 1][r] = f0.y;
        sinb[0][4 * w + 2][r] = f0.z;
        sinb[0][4 * w + 3][r] = f0.w;
    }
    __syncthreads();

    ull s1[3] = {0ull, 0ull, 0ull};
    ull s2[6] = {0ull, 0ull, 0ull, 0ull, 0ull, 0ull};

    for (int t = 0; t < T; ++t) {
        const int cur = t & 1, nxt = cur ^ 1;
        const int tn = (t < T - 1) ? (t + 1) : t;
        // prefetch next step's input chunk (consumed in Phase C)
        float4 nx = sp4[tn * 4 + w];

        // ---- Phase A: x = in@W1 + b1 + s1  (this warp's 3 unit-pairs) ----
        const float* ci = &sinb[cur][0][r];
        ull a0 = fadd2(s1[0], scw.B1[w][0]);
        ull a1 = fadd2(s1[1], scw.B1[w][1]);
        ull a2 = fadd2(s1[2], scw.B1[w][2]);
        #pragma unroll
        for (int kp = 0; kp < 8; ++kp) {
            const ulonglong2* q = reinterpret_cast<const ulonglong2*>(scw.W1m[w][kp]);
            ulonglong2 q0 = q[0], q1 = q[1], q2 = q[2];
            ull ik0 = dup2(ci[(2 * kp) * 32]);
            ull ik1 = dup2(ci[(2 * kp + 1) * 32]);
            a0 = ffma2(ik0, q0.x, a0); a1 = ffma2(ik0, q0.y, a1); a2 = ffma2(ik0, q1.x, a2);
            a0 = ffma2(ik1, q1.y, a0); a1 = ffma2(ik1, q2.x, a1); a2 = ffma2(ik1, q2.y, a2);
        }
        sx[3 * w + 0][r] = a0; sx[3 * w + 1][r] = a1; sx[3 * w + 2][r] = a2;
        __syncthreads();

        // ---- Phase B: ns1 = tanh(x@Wr1 + br1) ----
        ull b0 = scw.Br1[w][0], b1v = scw.Br1[w][1], b2v = scw.Br1[w][2];
        #pragma unroll
        for (int p = 0; p < 12; ++p) {
            const ulonglong2* q = reinterpret_cast<const ulonglong2*>(scw.Wr1m[w][p]);
            ulonglong2 q0 = q[0], q1 = q[1], q2 = q[2];
            float2 u = un2(sx[p][r]);
            ull k0 = dup2(u.x), k1 = dup2(u.y);
            b0  = ffma2(k0, q0.x, b0); b1v = ffma2(k0, q0.y, b1v); b2v = ffma2(k0, q1.x, b2v);
            b0  = ffma2(k1, q1.y, b0); b1v = ffma2(k1, q2.x, b1v); b2v = ffma2(k1, q2.y, b2v);
        }
        {
            float2 u0 = un2(b0), u1 = un2(b1v), u2 = un2(b2v);
            s1[0] = pk2(tanh_f(u0.x), tanh_f(u0.y));
            s1[1] = pk2(tanh_f(u1.x), tanh_f(u1.y));
            s1[2] = pk2(tanh_f(u2.x), tanh_f(u2.y));
        }
        sn[3 * w + 0][r] = s1[0]; sn[3 * w + 1][r] = s1[1]; sn[3 * w + 2][r] = s1[2];
        __syncthreads();

        // ---- Phase C: y = LN1-folded(ns1)@W2 + b2f + s2;  also stage next input ----
        ull c0 = 0, c1 = 0, c2 = 0, c3 = 0, c4 = 0, c5 = 0;
        ull sm2 = 0, sq2 = 0;
        #pragma unroll
        for (int p = 0; p < 12; ++p) {
            const ulonglong2* q = reinterpret_cast<const ulonglong2*>(scw.W2m[w][p]);
            ulonglong2 q0 = q[0], q1 = q[1], q2 = q[2];
            ulonglong2 q3 = q[3], q4 = q[4], q5 = q[5];
            ull npv = sn[p][r];
            sm2 = fadd2(sm2, npv); sq2 = ffma2(npv, npv, sq2);
            float2 u = un2(npv);
            ull k0 = dup2(u.x), k1 = dup2(u.y);
            c0 = ffma2(k0, q0.x, c0); c1 = ffma2(k0, q0.y, c1); c2 = ffma2(k0, q1.x, c2);
            c3 = ffma2(k0, q1.y, c3); c4 = ffma2(k0, q2.x, c4); c5 = ffma2(k0, q2.y, c5);
            c0 = ffma2(k1, q3.x, c0); c1 = ffma2(k1, q3.y, c1); c2 = ffma2(k1, q4.x, c2);
            c3 = ffma2(k1, q4.y, c3); c4 = ffma2(k1, q5.x, c4); c5 = ffma2(k1, q5.y, c5);
        }
        {
            float2 us = un2(sm2), uq = un2(sq2);
            float mu   = (us.x + us.y) * (1.0f / 24.0f);
            float var  = fmaf(-mu, mu, (uq.x + uq.y) * (1.0f / 24.0f));
            float rstd = rsqrtf(var + LN_EPS);
            ull mun = dup2(-mu), rsd = dup2(rstd);
            sy[6 * w + 0][r] = ffma2(rsd, ffma2(mun, scw.Cc[w][0], c0), fadd2(scw.B2f[w][0], s2[0]));
            sy[6 * w + 1][r] = ffma2(rsd, ffma2(mun, scw.Cc[w][1], c1), fadd2(scw.B2f[w][1], s2[1]));
            sy[6 * w + 2][r] = ffma2(rsd, ffma2(mun, scw.Cc[w][2], c2), fadd2(scw.B2f[w][2], s2[2]));
            sy[6 * w + 3][r] = ffma2(rsd, ffma2(mun, scw.Cc[w][3], c3), fadd2(scw.B2f[w][3], s2[3]));
            sy[6 * w + 4][r] = ffma2(rsd, ffma2(mun, scw.Cc[w][4], c4), fadd2(scw.B2f[w][4], s2[4]));
            sy[6 * w + 5][r] = ffma2(rsd, ffma2(mun, scw.Cc[w][5], c5), fadd2(scw.B2f[w][5], s2[5]));
        }
        // stage next input (read next step in Phase A; separated by bar3)
        sinb[nxt][4 * w + 0][r] = nx.x;
        sinb[nxt][4 * w + 1][r] = nx.y;
        sinb[nxt][4 * w + 2][r] = nx.z;
        sinb[nxt][4 * w + 3][r] = nx.w;
        __syncthreads();

        // ---- Phase D: ns2 = tanh(y@Wr2 + br2) ----  (no barrier after; see WAR analysis)
        ull d0 = scw.Br2[w][0], d1 = scw.Br2[w][1], d2 = scw.Br2[w][2];
        ull d3 = scw.Br2[w][3], d4 = scw.Br2[w][4], d5 = scw.Br2[w][5];
        #pragma unroll
        for (int p = 0; p < 24; ++p) {
            const ulonglong2* q = reinterpret_cast<const ulonglong2*>(scw.Wr2m[w][p]);
            ulonglong2 q0 = q[0], q1 = q[1], q2 = q[2];
            ulonglong2 q3 = q[3], q4 = q[4], q5 = q[5];
            float2 u = un2(sy[p][r]);
            ull k0 = dup2(u.x), k1 = dup2(u.y);
            d0 = ffma2(k0, q0.x, d0); d1 = ffma2(k0, q0.y, d1); d2 = ffma2(k0, q1.x, d2);
            d3 = ffma2(k0, q1.y, d3); d4 = ffma2(k0, q2.x, d4); d5 = ffma2(k0, q2.y, d5);
            d0 = ffma2(k1, q3.x, d0); d1 = ffma2(k1, q3.y, d1); d2 = ffma2(k1, q4.x, d2);
            d3 = ffma2(k1, q4.y, d3); d4 = ffma2(k1, q5.x, d4); d5 = ffma2(k1, q5.y, d5);
        }
        {
            float2 u;
            u = un2(d0); s2[0] = pk2(tanh_f(u.x), tanh_f(u.y));
            u = un2(d1); s2[1] = pk2(tanh_f(u.x), tanh_f(u.y));
            u = un2(d2); s2[2] = pk2(tanh_f(u.x), tanh_f(u.y));
            u = un2(d3); s2[3] = pk2(tanh_f(u.x), tanh_f(u.y));
            u = un2(d4); s2[4] = pk2(tanh_f(u.x), tanh_f(u.y));
            u = un2(d5); s2[5] = pk2(tanh_f(u.x), tanh_f(u.y));
        }
    }

    // ---- epilogue: sigmoid(LN(s2; g2,be2) @ Wout + bout) ----
    __syncthreads();   // protect sy rewrite below against other warps' Phase D reads
    #pragma unroll
    for (int j = 0; j < 6; ++j) sy[6 * w + j][r] = s2[j];
    __syncthreads();

    if (w == 0) {
        ull zp[24];
        #pragma unroll
        for (int p = 0; p < 24; ++p) zp[p] = sy[p][r];
        ull sm2 = zp[0], sq2 = fmul2(zp[0], zp[0]);
        #pragma unroll
        for (int p = 1; p < 24; ++p) { sm2 = fadd2(sm2, zp[p]); sq2 = ffma2(zp[p], zp[p], sq2); }
        float2 us = un2(sm2), uq = un2(sq2);
        float mu   = (us.x + us.y) * (1.0f / 48.0f);
        float var  = fmaf(-mu, mu, (uq.x + uq.y) * (1.0f / 48.0f));
        float rstd = rsqrtf(var + LN_EPS);
        ull mun = dup2(-mu), rsd = dup2(rstd);
        ull acc = 0;
        #pragma unroll
        for (int p = 0; p < 24; ++p) {
            ull h = fmul2(fadd2(zp[p], mun), rsd);
            h = ffma2(h, scw.G2[p], scw.Be2[p]);
            acc = ffma2(h, scw.Wo[p], acc);
        }
        float2 ua = un2(acc);
        float z = ua.x + ua.y + scw.bout;
        out[row] = __fdividef(1.0f, 1.0f + __expf(-z));
    }
}

extern "C" void kernel_launch(void* const* d_in, const int* in_sizes, int n_in,
                              void* d_out, int out_size)
{
    const float* seq  = (const float*)d_in[0];
    const float* W1   = (const float*)d_in[1];
    const float* b1   = (const float*)d_in[2];
    const float* Wr1  = (const float*)d_in[3];
    const float* br1  = (const float*)d_in[4];
    const float* g1   = (const float*)d_in[5];
    const float* be1  = (const float*)d_in[6];
    const float* W2   = (const float*)d_in[7];
    const float* b2   = (const float*)d_in[8];
    const float* Wr2  = (const float*)d_in[9];
    const float* br2  = (const float*)d_in[10];
    const float* g2   = (const float*)d_in[11];
    const float* be2  = (const float*)d_in[12];
    const float* Wout = (const float*)d_in[13];
    const float* bout = (const float*)d_in[14];

    prep_kernel<<<1, 256>>>(W1, b1, Wr1, br1, g1, be1,
                            W2, b2, Wr2, br2, g2, be2, Wout, bout);

    const int B = in_sizes[0] / (T * F);     // 8192
    rnn_main<<<B / 32, 128>>>(seq, (float*)d_out);
}

// round 4
// speedup vs baseline: 4.1107x; 1.1987x over previous
#include <cuda_runtime.h>

typedef unsigned long long ull;

static constexpr int T  = 256;
static constexpr int F  = 16;
static constexpr int U1 = 24;
static constexpr int U2 = 48;
#define LN_EPS 1e-3f

// ---------------- packed f32x2 helpers ----------------
__device__ __forceinline__ ull pk2(float lo, float hi) {
    ull r; asm("mov.b64 %0, {%1, %2};" : "=l"(r) : "f"(lo), "f"(hi)); return r;
}
__device__ __forceinline__ ull dup2(float v) { return pk2(v, v); }
__device__ __forceinline__ float2 un2(ull p) {
    float2 r; asm("mov.b64 {%0, %1}, %2;" : "=f"(r.x), "=f"(r.y) : "l"(p)); return r;
}
__device__ __forceinline__ ull ffma2(ull a, ull b, ull c) {
    ull d; asm("fma.rn.f32x2 %0, %1, %2, %3;" : "=l"(d) : "l"(a), "l"(b), "l"(c)); return d;
}
__device__ __forceinline__ ull fadd2(ull a, ull b) {
    ull d; asm("add.rn.f32x2 %0, %1, %2;" : "=l"(d) : "l"(a), "l"(b)); return d;
}
__device__ __forceinline__ ull fmul2(ull a, ull b) {
    ull d; asm("mul.rn.f32x2 %0, %1, %2;" : "=l"(d) : "l"(a), "l"(b)); return d;
}

// branch-free accurate tanh: 1 - 2/(1+e^{2x})
__device__ __forceinline__ float tanh_f(float x) {
    float e = __expf(2.0f * x);
    return 1.0f - __fdividef(2.0f, 1.0f + e);
}

// ---------------- packed weight bundle (global staging -> smem) ----------------
struct __align__(16) CW {
    ull W1m [4][8][6];    // [w][kp][j]: j0..2 = k=2kp pairs, j3..5 = k=2kp+1 pairs
    ull Wr1m[4][12][6];   // [w][p][j]:  k-rows 2p, 2p+1 (3 pairs each)
    ull W2m [4][12][12];  // [w][p][j]:  j0..5 row 2p, j6..11 row 2p+1 (g1-folded)
    ull Wr2m[4][24][12];  // [w][p][j]:  rows 2p, 2p+1 (6 pairs each)
    ull B1 [4][3];
    ull Br1[4][3];
    ull Br2[4][6];
    ull B2f[4][6];        // b2 + be1 @ W2
    ull Cc [4][6];        // column sums of folded W2
    ull G2 [24];
    ull Be2[24];
    ull Wo [24];
    float bout;
    float pad3[3];
};
__device__ CW d_stage;

__device__ __forceinline__ ull mkp(float lo, float hi) {
    return ((ull)__float_as_uint(hi) << 32) | __float_as_uint(lo);
}

// ---------------- prep kernel (unchanged from R3, validated) ----------------
__global__ void prep_kernel(const float* __restrict__ W1,  const float* __restrict__ b1,
                            const float* __restrict__ Wr1, const float* __restrict__ br1,
                            const float* __restrict__ g1,  const float* __restrict__ be1,
                            const float* __restrict__ W2,  const float* __restrict__ b2,
                            const float* __restrict__ Wr2, const float* __restrict__ br2,
                            const float* __restrict__ g2,  const float* __restrict__ be2,
                            const float* __restrict__ Wout, const float* __restrict__ bout)
{
    const int tid = threadIdx.x;  // 256 threads
    for (int idx = tid; idx < 4 * 8 * 6; idx += 256) {
        int w = idx / 48, kp = (idx / 6) % 8, j = idx % 6;
        int k = 2 * kp + (j >= 3), u = 6 * w + 2 * (j % 3);
        d_stage.W1m[w][kp][j] = mkp(W1[k * U1 + u], W1[k * U1 + u + 1]);
    }
    for (int idx = tid; idx < 4 * 12 * 6; idx += 256) {
        int w = idx / 72, p = (idx / 6) % 12, j = idx % 6;
        int k = 2 * p + (j >= 3), u = 6 * w + 2 * (j % 3);
        d_stage.Wr1m[w][p][j] = mkp(Wr1[k * U1 + u], Wr1[k * U1 + u + 1]);
    }
    for (int idx = tid; idx < 4 * 12 * 12; idx += 256) {
        int w = idx / 144, p = (idx / 12) % 12, j = idx % 12;
        int k = 2 * p + (j >= 6), u = 12 * w + 2 * (j % 6);
        d_stage.W2m[w][p][j] = mkp(g1[k] * W2[k * U2 + u], g1[k] * W2[k * U2 + u + 1]);
    }
    for (int idx = tid; idx < 4 * 24 * 12; idx += 256) {
        int w = idx / 288, p = (idx % 288) / 12, j = idx % 12;
        int k = 2 * p + (j >= 6), u = 12 * w + 2 * (j % 6);
        d_stage.Wr2m[w][p][j] = mkp(Wr2[k * U2 + u], Wr2[k * U2 + u + 1]);
    }
    for (int idx = tid; idx < 12; idx += 256) {
        int w = idx / 3, j = idx % 3, u = 6 * w + 2 * j;
        d_stage.B1[w][j]  = mkp(b1[u],  b1[u + 1]);
        d_stage.Br1[w][j] = mkp(br1[u], br1[u + 1]);
    }
    for (int idx = tid; idx < 24; idx += 256) {
        int w = idx / 6, j = idx % 6, u = 12 * w + 2 * j;
        float bfl = b2[u], bfh = b2[u + 1], cl = 0.f, ch = 0.f;
        for (int k = 0; k < U1; ++k) {
            bfl += be1[k] * W2[k * U2 + u];
            bfh += be1[k] * W2[k * U2 + u + 1];
            cl  += g1[k] * W2[k * U2 + u];
            ch  += g1[k] * W2[k * U2 + u + 1];
        }
        d_stage.Br2[w][j] = mkp(br2[u], br2[u + 1]);
        d_stage.B2f[w][j] = mkp(bfl, bfh);
        d_stage.Cc[w][j]  = mkp(cl, ch);
    }
    for (int idx = tid; idx < 24; idx += 256) {
        int u = 2 * idx;
        d_stage.G2[idx]  = mkp(g2[u],   g2[u + 1]);
        d_stage.Be2[idx] = mkp(be2[u],  be2[u + 1]);
        d_stage.Wo[idx]  = mkp(Wout[u], Wout[u + 1]);
    }
    if (tid == 0) { d_stage.bout = bout[0]; }
}

// ---------------- smem layout (dynamic; >48KB static cap) ----------------
struct SmemLayout {
    CW cw;
    ull sx[12][64];          // x pairs    [pair][row]
    ull sn[12][64];          // ns1 pairs
    ull sy[24][64];          // y pairs / final ns2 pairs
    float sinb[2][16][66];   // staged input [buf][feat][row(padded)]
};

// ---------------- main scan kernel ----------------
// CTA: 128 threads = 4 warps. lane r handles rows 2r,2r+1; warp = unit slice.
// 64 rows/CTA, grid=128 -> single wave.
__global__ __launch_bounds__(128, 1)
void rnn_main(const float* __restrict__ seq, float* __restrict__ out)
{
    extern __shared__ __align__(16) char smem_raw[];
    SmemLayout* S = reinterpret_cast<SmemLayout*>(smem_raw);

    const int tid = threadIdx.x;
    const int w = tid >> 5;
    const int r = tid & 31;
    const int rowbase = blockIdx.x * 64;

    // cooperative copy of packed weights into smem
    {
        const ull* gsrc = reinterpret_cast<const ull*>(&d_stage);
        ull* sdst = reinterpret_cast<ull*>(&S->cw);
        const int N = (int)(sizeof(CW) / 8);
        for (int i = tid; i < N; i += 128) sdst[i] = gsrc[i];
    }

    // per-thread global-load mapping: thread covers (row_l, chunk) and (row_l+32, chunk)
    const int row_l0 = tid >> 2, ch = tid & 3;
    const float4* gp0 = reinterpret_cast<const float4*>(
                            seq + (size_t)(rowbase + row_l0) * (T * F)) + ch;
    const float4* gp1 = reinterpret_cast<const float4*>(
                            seq + (size_t)(rowbase + row_l0 + 32) * (T * F)) + ch;

    // stage t=0 input
    {
        float4 f0 = gp0[0];
        float4 f1 = gp1[0];
        S->sinb[0][4 * ch + 0][row_l0] = f0.x;
        S->sinb[0][4 * ch + 1][row_l0] = f0.y;
        S->sinb[0][4 * ch + 2][row_l0] = f0.z;
        S->sinb[0][4 * ch + 3][row_l0] = f0.w;
        S->sinb[0][4 * ch + 0][row_l0 + 32] = f1.x;
        S->sinb[0][4 * ch + 1][row_l0 + 32] = f1.y;
        S->sinb[0][4 * ch + 2][row_l0 + 32] = f1.z;
        S->sinb[0][4 * ch + 3][row_l0 + 32] = f1.w;
    }
    __syncthreads();

    ull s1[2][3] = {{0,0,0},{0,0,0}};
    ull s2[2][6] = {{0,0,0,0,0,0},{0,0,0,0,0,0}};

    for (int t = 0; t < T; ++t) {
        const int cur = t & 1, nxt = cur ^ 1;
        const int tn = (t < T - 1) ? (t + 1) : t;
        float4 nx0 = gp0[tn * 4];
        float4 nx1 = gp1[tn * 4];

        // ---- Phase A: x = in@W1 + b1 + s1 (3 unit-pairs, 2 rows) ----
        ull a00 = fadd2(s1[0][0], S->cw.B1[w][0]);
        ull a01 = fadd2(s1[0][1], S->cw.B1[w][1]);
        ull a02 = fadd2(s1[0][2], S->cw.B1[w][2]);
        ull a10 = fadd2(s1[1][0], S->cw.B1[w][0]);
        ull a11 = fadd2(s1[1][1], S->cw.B1[w][1]);
        ull a12 = fadd2(s1[1][2], S->cw.B1[w][2]);
        #pragma unroll
        for (int kp = 0; kp < 8; ++kp) {
            const ulonglong2* q = reinterpret_cast<const ulonglong2*>(S->cw.W1m[w][kp]);
            ulonglong2 q0 = q[0], q1 = q[1], q2 = q[2];
            float2 f0 = *reinterpret_cast<const float2*>(&S->sinb[cur][2 * kp][2 * r]);
            float2 f1 = *reinterpret_cast<const float2*>(&S->sinb[cur][2 * kp + 1][2 * r]);
            ull k00 = dup2(f0.x), k01 = dup2(f0.y);   // feat 2kp, rows 0/1
            ull k10 = dup2(f1.x), k11 = dup2(f1.y);   // feat 2kp+1
            a00 = ffma2(k00, q0.x, a00); a01 = ffma2(k00, q0.y, a01); a02 = ffma2(k00, q1.x, a02);
            a00 = ffma2(k10, q1.y, a00); a01 = ffma2(k10, q2.x, a01); a02 = ffma2(k10, q2.y, a02);
            a10 = ffma2(k01, q0.x, a10); a11 = ffma2(k01, q0.y, a11); a12 = ffma2(k01, q1.x, a12);
            a10 = ffma2(k11, q1.y, a10); a11 = ffma2(k11, q2.x, a11); a12 = ffma2(k11, q2.y, a12);
        }
        *reinterpret_cast<ulonglong2*>(&S->sx[3 * w + 0][2 * r]) = make_ulonglong2(a00, a10);
        *reinterpret_cast<ulonglong2*>(&S->sx[3 * w + 1][2 * r]) = make_ulonglong2(a01, a11);
        *reinterpret_cast<ulonglong2*>(&S->sx[3 * w + 2][2 * r]) = make_ulonglong2(a02, a12);
        __syncthreads();

        // ---- Phase B: ns1 = tanh(x@Wr1 + br1) ----
        ull b00 = S->cw.Br1[w][0], b01 = S->cw.Br1[w][1], b02 = S->cw.Br1[w][2];
        ull b10 = b00, b11 = b01, b12 = b02;
        #pragma unroll
        for (int p = 0; p < 12; ++p) {
            const ulonglong2* q = reinterpret_cast<const ulonglong2*>(S->cw.Wr1m[w][p]);
            ulonglong2 q0 = q[0], q1 = q[1], q2 = q[2];
            ulonglong2 X = *reinterpret_cast<const ulonglong2*>(&S->sx[p][2 * r]);
            float2 u0 = un2(X.x), u1 = un2(X.y);
            ull k0 = dup2(u0.x), k1 = dup2(u0.y);
            b00 = ffma2(k0, q0.x, b00); b01 = ffma2(k0, q0.y, b01); b02 = ffma2(k0, q1.x, b02);
            b00 = ffma2(k1, q1.y, b00); b01 = ffma2(k1, q2.x, b01); b02 = ffma2(k1, q2.y, b02);
            ull m0 = dup2(u1.x), m1 = dup2(u1.y);
            b10 = ffma2(m0, q0.x, b10); b11 = ffma2(m0, q0.y, b11); b12 = ffma2(m0, q1.x, b12);
            b10 = ffma2(m1, q1.y, b10); b11 = ffma2(m1, q2.x, b11); b12 = ffma2(m1, q2.y, b12);
        }
        {
            float2 u;
            u = un2(b00); s1[0][0] = pk2(tanh_f(u.x), tanh_f(u.y));
            u = un2(b01); s1[0][1] = pk2(tanh_f(u.x), tanh_f(u.y));
            u = un2(b02); s1[0][2] = pk2(tanh_f(u.x), tanh_f(u.y));
            u = un2(b10); s1[1][0] = pk2(tanh_f(u.x), tanh_f(u.y));
            u = un2(b11); s1[1][1] = pk2(tanh_f(u.x), tanh_f(u.y));
            u = un2(b12); s1[1][2] = pk2(tanh_f(u.x), tanh_f(u.y));
        }
        *reinterpret_cast<ulonglong2*>(&S->sn[3 * w + 0][2 * r]) = make_ulonglong2(s1[0][0], s1[1][0]);
        *reinterpret_cast<ulonglong2*>(&S->sn[3 * w + 1][2 * r]) = make_ulonglong2(s1[0][1], s1[1][1]);
        *reinterpret_cast<ulonglong2*>(&S->sn[3 * w + 2][2 * r]) = make_ulonglong2(s1[0][2], s1[1][2]);
        __syncthreads();

        // ---- Phase C: y = LN1-folded(ns1)@W2 + b2f + s2 ----
        ull c0[2] = {0,0}, c1[2] = {0,0}, c2[2] = {0,0},
            c3[2] = {0,0}, c4[2] = {0,0}, c5[2] = {0,0};
        ull sm2[2] = {0,0}, sq2[2] = {0,0};
        #pragma unroll
        for (int p = 0; p < 12; ++p) {
            const ulonglong2* q = reinterpret_cast<const ulonglong2*>(S->cw.W2m[w][p]);
            ulonglong2 q0 = q[0], q1 = q[1], q2 = q[2];
            ulonglong2 q3 = q[3], q4 = q[4], q5 = q[5];
            ulonglong2 X = *reinterpret_cast<const ulonglong2*>(&S->sn[p][2 * r]);
            sm2[0] = fadd2(sm2[0], X.x); sq2[0] = ffma2(X.x, X.x, sq2[0]);
            sm2[1] = fadd2(sm2[1], X.y); sq2[1] = ffma2(X.y, X.y, sq2[1]);
            float2 u0 = un2(X.x), u1 = un2(X.y);
            ull k0 = dup2(u0.x), k1 = dup2(u0.y);
            c0[0] = ffma2(k0, q0.x, c0[0]); c1[0] = ffma2(k0, q0.y, c1[0]); c2[0] = ffma2(k0, q1.x, c2[0]);
            c3[0] = ffma2(k0, q1.y, c3[0]); c4[0] = ffma2(k0, q2.x, c4[0]); c5[0] = ffma2(k0, q2.y, c5[0]);
            c0[0] = ffma2(k1, q3.x, c0[0]); c1[0] = ffma2(k1, q3.y, c1[0]); c2[0] = ffma2(k1, q4.x, c2[0]);
            c3[0] = ffma2(k1, q4.y, c3[0]); c4[0] = ffma2(k1, q5.x, c4[0]); c5[0] = ffma2(k1, q5.y, c5[0]);
            ull m0 = dup2(u1.x), m1 = dup2(u1.y);
            c0[1] = ffma2(m0, q0.x, c0[1]); c1[1] = ffma2(m0, q0.y, c1[1]); c2[1] = ffma2(m0, q1.x, c2[1]);
            c3[1] = ffma2(m0, q1.y, c3[1]); c4[1] = ffma2(m0, q2.x, c4[1]); c5[1] = ffma2(m0, q2.y, c5[1]);
            c0[1] = ffma2(m1, q3.x, c0[1]); c1[1] = ffma2(m1, q3.y, c1[1]); c2[1] = ffma2(m1, q4.x, c2[1]);
            c3[1] = ffma2(m1, q4.y, c3[1]); c4[1] = ffma2(m1, q5.x, c4[1]); c5[1] = ffma2(m1, q5.y, c5[1]);
        }
        #pragma unroll
        for (int rho = 0; rho < 2; ++rho) {
            float2 us = un2(sm2[rho]), uq = un2(sq2[rho]);
            float mu   = (us.x + us.y) * (1.0f / 24.0f);
            float var  = fmaf(-mu, mu, (uq.x + uq.y) * (1.0f / 24.0f));
            float rstd = rsqrtf(var + LN_EPS);
            ull mun = dup2(-mu), rsd = dup2(rstd);
            c0[rho] = ffma2(rsd, ffma2(mun, S->cw.Cc[w][0], c0[rho]), fadd2(S->cw.B2f[w][0], s2[rho][0]));
            c1[rho] = ffma2(rsd, ffma2(mun, S->cw.Cc[w][1], c1[rho]), fadd2(S->cw.B2f[w][1], s2[rho][1]));
            c2[rho] = ffma2(rsd, ffma2(mun, S->cw.Cc[w][2], c2[rho]), fadd2(S->cw.B2f[w][2], s2[rho][2]));
            c3[rho] = ffma2(rsd, ffma2(mun, S->cw.Cc[w][3], c3[rho]), fadd2(S->cw.B2f[w][3], s2[rho][3]));
            c4[rho] = ffma2(rsd, ffma2(mun, S->cw.Cc[w][4], c4[rho]), fadd2(S->cw.B2f[w][4], s2[rho][4]));
            c5[rho] = ffma2(rsd, ffma2(mun, S->cw.Cc[w][5], c5[rho]), fadd2(S->cw.B2f[w][5], s2[rho][5]));
        }
        *reinterpret_cast<ulonglong2*>(&S->sy[6 * w + 0][2 * r]) = make_ulonglong2(c0[0], c0[1]);
        *reinterpret_cast<ulonglong2*>(&S->sy[6 * w + 1][2 * r]) = make_ulonglong2(c1[0], c1[1]);
        *reinterpret_cast<ulonglong2*>(&S->sy[6 * w + 2][2 * r]) = make_ulonglong2(c2[0], c2[1]);
        *reinterpret_cast<ulonglong2*>(&S->sy[6 * w + 3][2 * r]) = make_ulonglong2(c3[0], c3[1]);
        *reinterpret_cast<ulonglong2*>(&S->sy[6 * w + 4][2 * r]) = make_ulonglong2(c4[0], c4[1]);
        *reinterpret_cast<ulonglong2*>(&S->sy[6 * w + 5][2 * r]) = make_ulonglong2(c5[0], c5[1]);
        // stage next input
        S->sinb[nxt][4 * ch + 0][row_l0] = nx0.x;
        S->sinb[nxt][4 * ch + 1][row_l0] = nx0.y;
        S->sinb[nxt][4 * ch + 2][row_l0] = nx0.z;
        S->sinb[nxt][4 * ch + 3][row_l0] = nx0.w;
        S->sinb[nxt][4 * ch + 0][row_l0 + 32] = nx1.x;
        S->sinb[nxt][4 * ch + 1][row_l0 + 32] = nx1.y;
        S->sinb[nxt][4 * ch + 2][row_l0 + 32] = nx1.z;
        S->sinb[nxt][4 * ch + 3][row_l0 + 32] = nx1.w;
        __syncthreads();

        // ---- Phase D: ns2 = tanh(y@Wr2 + br2) ----
        ull d0[2], d1[2], d2[2], d3[2], d4[2], d5[2];
        d0[0] = d0[1] = S->cw.Br2[w][0];
        d1[0] = d1[1] = S->cw.Br2[w][1];
        d2[0] = d2[1] = S->cw.Br2[w][2];
        d3[0] = d3[1] = S->cw.Br2[w][3];
        d4[0] = d4[1] = S->cw.Br2[w][4];
        d5[0] = d5[1] = S->cw.Br2[w][5];
        #pragma unroll
        for (int p = 0; p < 24; ++p) {
            const ulonglong2* q = reinterpret_cast<const ulonglong2*>(S->cw.Wr2m[w][p]);
            ulonglong2 q0 = q[0], q1 = q[1], q2 = q[2];
            ulonglong2 q3 = q[3], q4 = q[4], q5 = q[5];
            ulonglong2 X = *reinterpret_cast<const ulonglong2*>(&S->sy[p][2 * r]);
            float2 u0 = un2(X.x), u1 = un2(X.y);
            ull k0 = dup2(u0.x), k1 = dup2(u0.y);
            d0[0] = ffma2(k0, q0.x, d0[0]); d1[0] = ffma2(k0, q0.y, d1[0]); d2[0] = ffma2(k0, q1.x, d2[0]);
            d3[0] = ffma2(k0, q1.y, d3[0]); d4[0] = ffma2(k0, q2.x, d4[0]); d5[0] = ffma2(k0, q2.y, d5[0]);
            d0[0] = ffma2(k1, q3.x, d0[0]); d1[0] = ffma2(k1, q3.y, d1[0]); d2[0] = ffma2(k1, q4.x, d2[0]);
            d3[0] = ffma2(k1, q4.y, d3[0]); d4[0] = ffma2(k1, q5.x, d4[0]); d5[0] = ffma2(k1, q5.y, d5[0]);
            ull m0 = dup2(u1.x), m1 = dup2(u1.y);
            d0[1] = ffma2(m0, q0.x, d0[1]); d1[1] = ffma2(m0, q0.y, d1[1]); d2[1] = ffma2(m0, q1.x, d2[1]);
            d3[1] = ffma2(m0, q1.y, d3[1]); d4[1] = ffma2(m0, q2.x, d4[1]); d5[1] = ffma2(m0, q2.y, d5[1]);
            d0[1] = ffma2(m1, q3.x, d0[1]); d1[1] = ffma2(m1, q3.y, d1[1]); d2[1] = ffma2(m1, q4.x, d2[1]);
            d3[1] = ffma2(m1, q4.y, d3[1]); d4[1] = ffma2(m1, q5.x, d4[1]); d5[1] = ffma2(m1, q5.y, d5[1]);
        }
        #pragma unroll
        for (int rho = 0; rho < 2; ++rho) {
            float2 u;
            u = un2(d0[rho]); s2[rho][0] = pk2(tanh_f(u.x), tanh_f(u.y));
            u = un2(d1[rho]); s2[rho][1] = pk2(tanh_f(u.x), tanh_f(u.y));
            u = un2(d2[rho]); s2[rho][2] = pk2(tanh_f(u.x), tanh_f(u.y));
            u = un2(d3[rho]); s2[rho][3] = pk2(tanh_f(u.x), tanh_f(u.y));
            u = un2(d4[rho]); s2[rho][4] = pk2(tanh_f(u.x), tanh_f(u.y));
            u = un2(d5[rho]); s2[rho][5] = pk2(tanh_f(u.x), tanh_f(u.y));
        }
    }

    // ---- epilogue: sigmoid(LN(s2; g2,be2) @ Wout + bout) ----
    __syncthreads();
    #pragma unroll
    for (int j = 0; j < 6; ++j)
        *reinterpret_cast<ulonglong2*>(&S->sy[6 * w + j][2 * r]) =
            make_ulonglong2(s2[0][j], s2[1][j]);
    __syncthreads();

    if (w == 0) {
        ull zp[2][24];
        #pragma unroll
        for (int p = 0; p < 24; ++p) {
            ulonglong2 X = *reinterpret_cast<const ulonglong2*>(&S->sy[p][2 * r]);
            zp[0][p] = X.x; zp[1][p] = X.y;
        }
        float res[2];
        #pragma unroll
        for (int rho = 0; rho < 2; ++rho) {
            ull sm2 = zp[rho][0], sq2 = fmul2(zp[rho][0], zp[rho][0]);
            #pragma unroll
            for (int p = 1; p < 24; ++p) {
                sm2 = fadd2(sm2, zp[rho][p]);
                sq2 = ffma2(zp[rho][p], zp[rho][p], sq2);
            }
            float2 us = un2(sm2), uq = un2(sq2);
            float mu   = (us.x + us.y) * (1.0f / 48.0f);
            float var  = fmaf(-mu, mu, (uq.x + uq.y) * (1.0f / 48.0f));
            float rstd = rsqrtf(var + LN_EPS);
            ull mun = dup2(-mu), rsd = dup2(rstd);
            ull acc = 0;
            #pragma unroll
            for (int p = 0; p < 24; ++p) {
                ull h = fmul2(fadd2(zp[rho][p], mun), rsd);
                h = ffma2(h, S->cw.G2[p], S->cw.Be2[p]);
                acc = ffma2(h, S->cw.Wo[p], acc);
            }
            float2 ua = un2(acc);
            float z = ua.x + ua.y + S->cw.bout;
            res[rho] = __fdividef(1.0f, 1.0f + __expf(-z));
        }
        *reinterpret_cast<float2*>(&out[rowbase + 2 * r]) = make_float2(res[0], res[1]);
    }
}

extern "C" void kernel_launch(void* const* d_in, const int* in_sizes, int n_in,
                              void* d_out, int out_size)
{
    const float* seq  = (const float*)d_in[0];
    const float* W1   = (const float*)d_in[1];
    const float* b1   = (const float*)d_in[2];
    const float* Wr1  = (const float*)d_in[3];
    const float* br1  = (const float*)d_in[4];
    const float* g1   = (const float*)d_in[5];
    const float* be1  = (const float*)d_in[6];
    const float* W2   = (const float*)d_in[7];
    const float* b2   = (const float*)d_in[8];
    const float* Wr2  = (const float*)d_in[9];
    const float* br2  = (const float*)d_in[10];
    const float* g2   = (const float*)d_in[11];
    const float* be2  = (const float*)d_in[12];
    const float* Wout = (const float*)d_in[13];
    const float* bout = (const float*)d_in[14];

    prep_kernel<<<1, 256>>>(W1, b1, Wr1, br1, g1, be1,
                            W2, b2, Wr2, br2, g2, be2, Wout, bout);

    static int smem_configured = 0;
    if (!smem_configured) {
        cudaFuncSetAttribute(rnn_main, cudaFuncAttributeMaxDynamicSharedMemorySize,
                             (int)sizeof(SmemLayout));
        smem_configured = 1;
    }

    const int B = in_sizes[0] / (T * F);     // 8192
    rnn_main<<<B / 64, 128, sizeof(SmemLayout)>>>(seq, (float*)d_out);
}

// round 5
// speedup vs baseline: 4.1340x; 1.0057x over previous
#include <cuda_runtime.h>

typedef unsigned long long ull;

static constexpr int T  = 256;
static constexpr int F  = 16;
static constexpr int U1 = 24;
static constexpr int U2 = 48;
#define LN_EPS 1e-3f

// ---------------- packed f32x2 helpers ----------------
__device__ __forceinline__ ull pk2(float lo, float hi) {
    ull r; asm("mov.b64 %0, {%1, %2};" : "=l"(r) : "f"(lo), "f"(hi)); return r;
}
__device__ __forceinline__ ull dup2(float v) { return pk2(v, v); }
__device__ __forceinline__ float2 un2(ull p) {
    float2 r; asm("mov.b64 {%0, %1}, %2;" : "=f"(r.x), "=f"(r.y) : "l"(p)); return r;
}
__device__ __forceinline__ ull ffma2(ull a, ull b, ull c) {
    ull d; asm("fma.rn.f32x2 %0, %1, %2, %3;" : "=l"(d) : "l"(a), "l"(b), "l"(c)); return d;
}
__device__ __forceinline__ ull fadd2(ull a, ull b) {
    ull d; asm("add.rn.f32x2 %0, %1, %2;" : "=l"(d) : "l"(a), "l"(b)); return d;
}
__device__ __forceinline__ ull fmul2(ull a, ull b) {
    ull d; asm("mul.rn.f32x2 %0, %1, %2;" : "=l"(d) : "l"(a), "l"(b)); return d;
}

// branch-free accurate tanh: 1 - 2/(1+e^{2x})
__device__ __forceinline__ float tanh_f(float x) {
    float e = __expf(2.0f * x);
    return 1.0f - __fdividef(2.0f, 1.0f + e);
}

// ---------------- packed weight bundle (global staging -> smem) ----------------
struct __align__(16) CW {
    ull W1m [4][8][6];    // [w][kp][j]: j0..2 = k=2kp pairs, j3..5 = k=2kp+1 pairs
    ull Wr1m[4][12][6];   // [w][p][j]:  k-rows 2p, 2p+1 (3 pairs each)
    ull W2m [4][12][12];  // [w][p][j]:  j0..5 row 2p, j6..11 row 2p+1 (g1-folded)
    ull Wr2m[4][24][12];  // [w][p][j]:  rows 2p, 2p+1 (6 pairs each)
    ull B1 [4][3];
    ull Br1[4][3];
    ull Br2[4][6];
    ull B2f[4][6];        // b2 + be1 @ W2
    ull Cc [4][6];        // column sums of folded W2
    ull G2 [24];
    ull Be2[24];
    ull Wo [24];
    float bout;
    float pad3[3];
};
__device__ CW d_stage;

__device__ __forceinline__ ull mkp(float lo, float hi) {
    return ((ull)__float_as_uint(hi) << 32) | __float_as_uint(lo);
}

// ---------------- prep kernel (unchanged from R3, validated) ----------------
__global__ void prep_kernel(const float* __restrict__ W1,  const float* __restrict__ b1,
                            const float* __restrict__ Wr1, const float* __restrict__ br1,
                            const float* __restrict__ g1,  const float* __restrict__ be1,
                            const float* __restrict__ W2,  const float* __restrict__ b2,
                            const float* __restrict__ Wr2, const float* __restrict__ br2,
                            const float* __restrict__ g2,  const float* __restrict__ be2,
                            const float* __restrict__ Wout, const float* __restrict__ bout)
{
    const int tid = threadIdx.x;  // 256 threads
    for (int idx = tid; idx < 4 * 8 * 6; idx += 256) {
        int w = idx / 48, kp = (idx / 6) % 8, j = idx % 6;
        int k = 2 * kp + (j >= 3), u = 6 * w + 2 * (j % 3);
        d_stage.W1m[w][kp][j] = mkp(W1[k * U1 + u], W1[k * U1 + u + 1]);
    }
    for (int idx = tid; idx < 4 * 12 * 6; idx += 256) {
        int w = idx / 72, p = (idx / 6) % 12, j = idx % 6;
        int k = 2 * p + (j >= 3), u = 6 * w + 2 * (j % 3);
        d_stage.Wr1m[w][p][j] = mkp(Wr1[k * U1 + u], Wr1[k * U1 + u + 1]);
    }
    for (int idx = tid; idx < 4 * 12 * 12; idx += 256) {
        int w = idx / 144, p = (idx / 12) % 12, j = idx % 12;
        int k = 2 * p + (j >= 6), u = 12 * w + 2 * (j % 6);
        d_stage.W2m[w][p][j] = mkp(g1[k] * W2[k * U2 + u], g1[k] * W2[k * U2 + u + 1]);
    }
    for (int idx = tid; idx < 4 * 24 * 12; idx += 256) {
        int w = idx / 288, p = (idx % 288) / 12, j = idx % 12;
        int k = 2 * p + (j >= 6), u = 12 * w + 2 * (j % 6);
        d_stage.Wr2m[w][p][j] = mkp(Wr2[k * U2 + u], Wr2[k * U2 + u + 1]);
    }
    for (int idx = tid; idx < 12; idx += 256) {
        int w = idx / 3, j = idx % 3, u = 6 * w + 2 * j;
        d_stage.B1[w][j]  = mkp(b1[u],  b1[u + 1]);
        d_stage.Br1[w][j] = mkp(br1[u], br1[u + 1]);
    }
    for (int idx = tid; idx < 24; idx += 256) {
        int w = idx / 6, j = idx % 6, u = 12 * w + 2 * j;
        float bfl = b2[u], bfh = b2[u + 1], cl = 0.f, ch = 0.f;
        for (int k = 0; k < U1; ++k) {
            bfl += be1[k] * W2[k * U2 + u];
            bfh += be1[k] * W2[k * U2 + u + 1];
            cl  += g1[k] * W2[k * U2 + u];
            ch  += g1[k] * W2[k * U2 + u + 1];
        }
        d_stage.Br2[w][j] = mkp(br2[u], br2[u + 1]);
        d_stage.B2f[w][j] = mkp(bfl, bfh);
        d_stage.Cc[w][j]  = mkp(cl, ch);
    }
    for (int idx = tid; idx < 24; idx += 256) {
        int u = 2 * idx;
        d_stage.G2[idx]  = mkp(g2[u],   g2[u + 1]);
        d_stage.Be2[idx] = mkp(be2[u],  be2[u + 1]);
        d_stage.Wo[idx]  = mkp(Wout[u], Wout[u + 1]);
    }
    if (tid == 0) { d_stage.bout = bout[0]; }
}

// ---------------- smem layout (dynamic; >48KB static cap) ----------------
struct SmemLayout {
    CW cw;
    ull sx[12][64];          // x pairs    [pair][row]
    ull sn[12][64];          // ns1 pairs
    ull sy[24][64];          // y pairs / final ns2 pairs
    float sinb[2][16][66];   // staged input [buf][feat][row(padded)]
};

// ---------------- main scan kernel ----------------
// CTA: 128 threads = 4 warps. lane r handles rows 2r,2r+1; warp = unit slice.
// 64 rows/CTA, grid=128 -> single wave.
__global__ __launch_bounds__(128, 1)
void rnn_main(const float* __restrict__ seq, float* __restrict__ out)
{
    extern __shared__ __align__(16) char smem_raw[];
    SmemLayout* S = reinterpret_cast<SmemLayout*>(smem_raw);

    const int tid = threadIdx.x;
    const int w = tid >> 5;
    const int r = tid & 31;
    const int rowbase = blockIdx.x * 64;

    // cooperative copy of packed weights into smem
    {
        const ull* gsrc = reinterpret_cast<const ull*>(&d_stage);
        ull* sdst = reinterpret_cast<ull*>(&S->cw);
        const int N = (int)(sizeof(CW) / 8);
        for (int i = tid; i < N; i += 128) sdst[i] = gsrc[i];
    }

    // per-thread global-load mapping: thread covers (row_l, chunk) and (row_l+32, chunk)
    const int row_l0 = tid >> 2, ch = tid & 3;
    const float4* gp0 = reinterpret_cast<const float4*>(
                            seq + (size_t)(rowbase + row_l0) * (T * F)) + ch;
    const float4* gp1 = reinterpret_cast<const float4*>(
                            seq + (size_t)(rowbase + row_l0 + 32) * (T * F)) + ch;

    // stage t=0 input
    {
        float4 f0 = gp0[0];
        float4 f1 = gp1[0];
        S->sinb[0][4 * ch + 0][row_l0] = f0.x;
        S->sinb[0][4 * ch + 1][row_l0] = f0.y;
        S->sinb[0][4 * ch + 2][row_l0] = f0.z;
        S->sinb[0][4 * ch + 3][row_l0] = f0.w;
        S->sinb[0][4 * ch + 0][row_l0 + 32] = f1.x;
        S->sinb[0][4 * ch + 1][row_l0 + 32] = f1.y;
        S->sinb[0][4 * ch + 2][row_l0 + 32] = f1.z;
        S->sinb[0][4 * ch + 3][row_l0 + 32] = f1.w;
    }
    __syncthreads();

    ull s1[2][3] = {{0,0,0},{0,0,0}};
    ull s2[2][6] = {{0,0,0,0,0,0},{0,0,0,0,0,0}};

    for (int t = 0; t < T; ++t) {
        const int cur = t & 1, nxt = cur ^ 1;
        const int tn = (t < T - 1) ? (t + 1) : t;
        float4 nx0 = gp0[tn * 4];
        float4 nx1 = gp1[tn * 4];

        // ---- Phase A: x = in@W1 + b1 + s1 (3 unit-pairs, 2 rows) ----
        ull a00 = fadd2(s1[0][0], S->cw.B1[w][0]);
        ull a01 = fadd2(s1[0][1], S->cw.B1[w][1]);
        ull a02 = fadd2(s1[0][2], S->cw.B1[w][2]);
        ull a10 = fadd2(s1[1][0], S->cw.B1[w][0]);
        ull a11 = fadd2(s1[1][1], S->cw.B1[w][1]);
        ull a12 = fadd2(s1[1][2], S->cw.B1[w][2]);
        #pragma unroll
        for (int kp = 0; kp < 8; ++kp) {
            const ulonglong2* q = reinterpret_cast<const ulonglong2*>(S->cw.W1m[w][kp]);
            ulonglong2 q0 = q[0], q1 = q[1], q2 = q[2];
            float2 f0 = *reinterpret_cast<const float2*>(&S->sinb[cur][2 * kp][2 * r]);
            float2 f1 = *reinterpret_cast<const float2*>(&S->sinb[cur][2 * kp + 1][2 * r]);
            ull k00 = dup2(f0.x), k01 = dup2(f0.y);   // feat 2kp, rows 0/1
            ull k10 = dup2(f1.x), k11 = dup2(f1.y);   // feat 2kp+1
            a00 = ffma2(k00, q0.x, a00); a01 = ffma2(k00, q0.y, a01); a02 = ffma2(k00, q1.x, a02);
            a00 = ffma2(k10, q1.y, a00); a01 = ffma2(k10, q2.x, a01); a02 = ffma2(k10, q2.y, a02);
            a10 = ffma2(k01, q0.x, a10); a11 = ffma2(k01, q0.y, a11); a12 = ffma2(k01, q1.x, a12);
            a10 = ffma2(k11, q1.y, a10); a11 = ffma2(k11, q2.x, a11); a12 = ffma2(k11, q2.y, a12);
        }
        *reinterpret_cast<ulonglong2*>(&S->sx[3 * w + 0][2 * r]) = make_ulonglong2(a00, a10);
        *reinterpret_cast<ulonglong2*>(&S->sx[3 * w + 1][2 * r]) = make_ulonglong2(a01, a11);
        *reinterpret_cast<ulonglong2*>(&S->sx[3 * w + 2][2 * r]) = make_ulonglong2(a02, a12);
        __syncthreads();

        // ---- Phase B: ns1 = tanh(x@Wr1 + br1) ----
        ull b00 = S->cw.Br1[w][0], b01 = S->cw.Br1[w][1], b02 = S->cw.Br1[w][2];
        ull b10 = b00, b11 = b01, b12 = b02;
        #pragma unroll
        for (int p = 0; p < 12; ++p) {
            const ulonglong2* q = reinterpret_cast<const ulonglong2*>(S->cw.Wr1m[w][p]);
            ulonglong2 q0 = q[0], q1 = q[1], q2 = q[2];
            ulonglong2 X = *reinterpret_cast<const ulonglong2*>(&S->sx[p][2 * r]);
            float2 u0 = un2(X.x), u1 = un2(X.y);
            ull k0 = dup2(u0.x), k1 = dup2(u0.y);
            b00 = ffma2(k0, q0.x, b00); b01 = ffma2(k0, q0.y, b01); b02 = ffma2(k0, q1.x, b02);
            b00 = ffma2(k1, q1.y, b00); b01 = ffma2(k1, q2.x, b01); b02 = ffma2(k1, q2.y, b02);
            ull m0 = dup2(u1.x), m1 = dup2(u1.y);
            b10 = ffma2(m0, q0.x, b10); b11 = ffma2(m0, q0.y, b11); b12 = ffma2(m0, q1.x, b12);
            b10 = ffma2(m1, q1.y, b10); b11 = ffma2(m1, q2.x, b11); b12 = ffma2(m1, q2.y, b12);
        }
        {
            float2 u;
            u = un2(b00); s1[0][0] = pk2(tanh_f(u.x), tanh_f(u.y));
            u = un2(b01); s1[0][1] = pk2(tanh_f(u.x), tanh_f(u.y));
            u = un2(b02); s1[0][2] = pk2(tanh_f(u.x), tanh_f(u.y));
            u = un2(b10); s1[1][0] = pk2(tanh_f(u.x), tanh_f(u.y));
            u = un2(b11); s1[1][1] = pk2(tanh_f(u.x), tanh_f(u.y));
            u = un2(b12); s1[1][2] = pk2(tanh_f(u.x), tanh_f(u.y));
        }
        *reinterpret_cast<ulonglong2*>(&S->sn[3 * w + 0][2 * r]) = make_ulonglong2(s1[0][0], s1[1][0]);
        *reinterpret_cast<ulonglong2*>(&S->sn[3 * w + 1][2 * r]) = make_ulonglong2(s1[0][1], s1[1][1]);
        *reinterpret_cast<ulonglong2*>(&S->sn[3 * w + 2][2 * r]) = make_ulonglong2(s1[0][2], s1[1][2]);
        __syncthreads();

        // ---- Phase C: y = LN1-folded(ns1)@W2 + b2f + s2 ----
        ull c0[2] = {0,0}, c1[2] = {0,0}, c2[2] = {0,0},
            c3[2] = {0,0}, c4[2] = {0,0}, c5[2] = {0,0};
        ull sm2[2] = {0,0}, sq2[2] = {0,0};
        #pragma unroll
        for (int p = 0; p < 12; ++p) {
            const ulonglong2* q = reinterpret_cast<const ulonglong2*>(S->cw.W2m[w][p]);
            ulonglong2 q0 = q[0], q1 = q[1], q2 = q[2];
            ulonglong2 q3 = q[3], q4 = q[4], q5 = q[5];
            ulonglong2 X = *reinterpret_cast<const ulonglong2*>(&S->sn[p][2 * r]);
            sm2[0] = fadd2(sm2[0], X.x); sq2[0] = ffma2(X.x, X.x, sq2[0]);
            sm2[1] = fadd2(sm2[1], X.y); sq2[1] = ffma2(X.y, X.y, sq2[1]);
            float2 u0 = un2(X.x), u1 = un2(X.y);
            ull k0 = dup2(u0.x), k1 = dup2(u0.y);
            c0[0] = ffma2(k0, q0.x, c0[0]); c1[0] = ffma2(k0, q0.y, c1[0]); c2[0] = ffma2(k0, q1.x, c2[0]);
            c3[0] = ffma2(k0, q1.y, c3[0]); c4[0] = ffma2(k0, q2.x, c4[0]); c5[0] = ffma2(k0, q2.y, c5[0]);
            c0[0] = ffma2(k1, q3.x, c0[0]); c1[0] = ffma2(k1, q3.y, c1[0]); c2[0] = ffma2(k1, q4.x, c2[0]);
            c3[0] = ffma2(k1, q4.y, c3[0]); c4[0] = ffma2(k1, q5.x, c4[0]); c5[0] = ffma2(k1, q5.y, c5[0]);
            ull m0 = dup2(u1.x), m1 = dup2(u1.y);
            c0[1] = ffma2(m0, q0.x, c0[1]); c1[1] = ffma2(m0, q0.y, c1[1]); c2[1] = ffma2(m0, q1.x, c2[1]);
            c3[1] = ffma2(m0, q1.y, c3[1]); c4[1] = ffma2(m0, q2.x, c4[1]); c5[1] = ffma2(m0, q2.y, c5[1]);
            c0[1] = ffma2(m1, q3.x, c0[1]); c1[1] = ffma2(m1, q3.y, c1[1]); c2[1] = ffma2(m1, q4.x, c2[1]);
            c3[1] = ffma2(m1, q4.y, c3[1]); c4[1] = ffma2(m1, q5.x, c4[1]); c5[1] = ffma2(m1, q5.y, c5[1]);
        }
        #pragma unroll
        for (int rho = 0; rho < 2; ++rho) {
            float2 us = un2(sm2[rho]), uq = un2(sq2[rho]);
            float mu   = (us.x + us.y) * (1.0f / 24.0f);
            float var  = fmaf(-mu, mu, (uq.x + uq.y) * (1.0f / 24.0f));
            float rstd = rsqrtf(var + LN_EPS);
            ull mun = dup2(-mu), rsd = dup2(rstd);
            c0[rho] = ffma2(rsd, ffma2(mun, S->cw.Cc[w][0], c0[rho]), fadd2(S->cw.B2f[w][0], s2[rho][0]));
            c1[rho] = ffma2(rsd, ffma2(mun, S->cw.Cc[w][1], c1[rho]), fadd2(S->cw.B2f[w][1], s2[rho][1]));
            c2[rho] = ffma2(rsd, ffma2(mun, S->cw.Cc[w][2], c2[rho]), fadd2(S->cw.B2f[w][2], s2[rho][2]));
            c3[rho] = ffma2(rsd, ffma2(mun, S->cw.Cc[w][3], c3[rho]), fadd2(S->cw.B2f[w][3], s2[rho][3]));
            c4[rho] = ffma2(rsd, ffma2(mun, S->cw.Cc[w][4], c4[rho]), fadd2(S->cw.B2f[w][4], s2[rho][4]));
            c5[rho] = ffma2(rsd, ffma2(mun, S->cw.Cc[w][5], c5[rho]), fadd2(S->cw.B2f[w][5], s2[rho][5]));
        }
        *reinterpret_cast<ulonglong2*>(&S->sy[6 * w + 0][2 * r]) = make_ulonglong2(c0[0], c0[1]);
        *reinterpret_cast<ulonglong2*>(&S->sy[6 * w + 1][2 * r]) = make_ulonglong2(c1[0], c1[1]);
        *reinterpret_cast<ulonglong2*>(&S->sy[6 * w + 2][2 * r]) = make_ulonglong2(c2[0], c2[1]);
        *reinterpret_cast<ulonglong2*>(&S->sy[6 * w + 3][2 * r]) = make_ulonglong2(c3[0], c3[1]);
        *reinterpret_cast<ulonglong2*>(&S->sy[6 * w + 4][2 * r]) = make_ulonglong2(c4[0], c4[1]);
        *reinterpret_cast<ulonglong2*>(&S->sy[6 * w + 5][2 * r]) = make_ulonglong2(c5[0], c5[1]);
        // stage next input
        S->sinb[nxt][4 * ch + 0][row_l0] = nx0.x;
        S->sinb[nxt][4 * ch + 1][row_l0] = nx0.y;
        S->sinb[nxt][4 * ch + 2][row_l0] = nx0.z;
        S->sinb[nxt][4 * ch + 3][row_l0] = nx0.w;
        S->sinb[nxt][4 * ch + 0][row_l0 + 32] = nx1.x;
        S->sinb[nxt][4 * ch + 1][row_l0 + 32] = nx1.y;
        S->sinb[nxt][4 * ch + 2][row_l0 + 32] = nx1.z;
        S->sinb[nxt][4 * ch + 3][row_l0 + 32] = nx1.w;
        __syncthreads();

        // ---- Phase D: ns2 = tanh(y@Wr2 + br2) ----
        ull d0[2], d1[2], d2[2], d3[2], d4[2], d5[2];
        d0[0] = d0[1] = S->cw.Br2[w][0];
        d1[0] = d1[1] = S->cw.Br2[w][1];
        d2[0] = d2[1] = S->cw.Br2[w][2];
        d3[0] = d3[1] = S->cw.Br2[w][3];
        d4[0] = d4[1] = S->cw.Br2[w][4];
        d5[0] = d5[1] = S->cw.Br2[w][5];
        #pragma unroll
        for (int p = 0; p < 24; ++p) {
            const ulonglong2* q = reinterpret_cast<const ulonglong2*>(S->cw.Wr2m[w][p]);
            ulonglong2 q0 = q[0], q1 = q[1], q2 = q[2];
            ulonglong2 q3 = q[3], q4 = q[4], q5 = q[5];
            ulonglong2 X = *reinterpret_cast<const ulonglong2*>(&S->sy[p][2 * r]);
            float2 u0 = un2(X.x), u1 = un2(X.y);
            ull k0 = dup2(u0.x), k1 = dup2(u0.y);
            d0[0] = ffma2(k0, q0.x, d0[0]); d1[0] = ffma2(k0, q0.y, d1[0]); d2[0] = ffma2(k0, q1.x, d2[0]);
            d3[0] = ffma2(k0, q1.y, d3[0]); d4[0] = ffma2(k0, q2.x, d4[0]); d5[0] = ffma2(k0, q2.y, d5[0]);
            d0[0] = ffma2(k1, q3.x, d0[0]); d1[0] = ffma2(k1, q3.y, d1[0]); d2[0] = ffma2(k1, q4.x, d2[0]);
            d3[0] = ffma2(k1, q4.y, d3[0]); d4[0] = ffma2(k1, q5.x, d4[0]); d5[0] = ffma2(k1, q5.y, d5[0]);
            ull m0 = dup2(u1.x), m1 = dup2(u1.y);
            d0[1] = ffma2(m0, q0.x, d0[1]); d1[1] = ffma2(m0, q0.y, d1[1]); d2[1] = ffma2(m0, q1.x, d2[1]);
            d3[1] = ffma2(m0, q1.y, d3[1]); d4[1] = ffma2(m0, q2.x, d4[1]); d5[1] = ffma2(m0, q2.y, d5[1]);
            d0[1] = ffma2(m1, q3.x, d0[1]); d1[1] = ffma2(m1, q3.y, d1[1]); d2[1] = ffma2(m1, q4.x, d2[1]);
            d3[1] = ffma2(m1, q4.y, d3[1]); d4[1] = ffma2(m1, q5.x, d4[1]); d5[1] = ffma2(m1, q5.y, d5[1]);
        }
        #pragma unroll
        for (int rho = 0; rho < 2; ++rho) {
            float2 u;
            u = un2(d0[rho]); s2[rho][0] = pk2(tanh_f(u.x), tanh_f(u.y));
            u = un2(d1[rho]); s2[rho][1] = pk2(tanh_f(u.x), tanh_f(u.y));
            u = un2(d2[rho]); s2[rho][2] = pk2(tanh_f(u.x), tanh_f(u.y));
            u = un2(d3[rho]); s2[rho][3] = pk2(tanh_f(u.x), tanh_f(u.y));
            u = un2(d4[rho]); s2[rho][4] = pk2(tanh_f(u.x), tanh_f(u.y));
            u = un2(d5[rho]); s2[rho][5] = pk2(tanh_f(u.x), tanh_f(u.y));
        }
    }

    // ---- epilogue: sigmoid(LN(s2; g2,be2) @ Wout + bout) ----
    __syncthreads();
    #pragma unroll
    for (int j = 0; j < 6; ++j)
        *reinterpret_cast<ulonglong2*>(&S->sy[6 * w + j][2 * r]) =
            make_ulonglong2(s2[0][j], s2[1][j]);
    __syncthreads();

    if (w == 0) {
        ull zp[2][24];
        #pragma unroll
        for (int p = 0; p < 24; ++p) {
            ulonglong2 X = *reinterpret_cast<const ulonglong2*>(&S->sy[p][2 * r]);
            zp[0][p] = X.x; zp[1][p] = X.y;
        }
        float res[2];
        #pragma unroll
        for (int rho = 0; rho < 2; ++rho) {
            ull sm2 = zp[rho][0], sq2 = fmul2(zp[rho][0], zp[rho][0]);
            #pragma unroll
            for (int p = 1; p < 24; ++p) {
                sm2 = fadd2(sm2, zp[rho][p]);
                sq2 = ffma2(zp[rho][p], zp[rho][p], sq2);
            }
            float2 us = un2(sm2), uq = un2(sq2);
            float mu   = (us.x + us.y) * (1.0f / 48.0f);
            float var  = fmaf(-mu, mu, (uq.x + uq.y) * (1.0f / 48.0f));
            float rstd = rsqrtf(var + LN_EPS);
            ull mun = dup2(-mu), rsd = dup2(rstd);
            ull acc = 0;
            #pragma unroll
            for (int p = 0; p < 24; ++p) {
                ull h = fmul2(fadd2(zp[rho][p], mun), rsd);
                h = ffma2(h, S->cw.G2[p], S->cw.Be2[p]);
                acc = ffma2(h, S->cw.Wo[p], acc);
            }
            float2 ua = un2(acc);
            float z = ua.x + ua.y + S->cw.bout;
            res[rho] = __fdividef(1.0f, 1.0f + __expf(-z));
        }
        *reinterpret_cast<float2*>(&out[rowbase + 2 * r]) = make_float2(res[0], res[1]);
    }
}

extern "C" void kernel_launch(void* const* d_in, const int* in_sizes, int n_in,
                              void* d_out, int out_size)
{
    const float* seq  = (const float*)d_in[0];
    const float* W1   = (const float*)d_in[1];
    const float* b1   = (const float*)d_in[2];
    const float* Wr1  = (const float*)d_in[3];
    const float* br1  = (const float*)d_in[4];
    const float* g1   = (const float*)d_in[5];
    const float* be1  = (const float*)d_in[6];
    const float* W2   = (const float*)d_in[7];
    const float* b2   = (const float*)d_in[8];
    const float* Wr2  = (const float*)d_in[9];
    const float* br2  = (const float*)d_in[10];
    const float* g2   = (const float*)d_in[11];
    const float* be2  = (const float*)d_in[12];
    const float* Wout = (const float*)d_in[13];
    const float* bout = (const float*)d_in[14];

    prep_kernel<<<1, 256>>>(W1, b1, Wr1, br1, g1, be1,
                            W2, b2, Wr2, br2, g2, be2, Wout, bout);

    static int smem_configured = 0;
    if (!smem_configured) {
        cudaFuncSetAttribute(rnn_main, cudaFuncAttributeMaxDynamicSharedMemorySize,
                             (int)sizeof(SmemLayout));
        smem_configured = 1;
    }

    const int B = in_sizes[0] / (T * F);     // 8192
    rnn_main<<<B / 64, 128, sizeof(SmemLayout)>>>(seq, (float*)d_out);
}